// round 7
// baseline (speedup 1.0000x reference)
#include <cuda_runtime.h>
#include <cuda_bf16.h>
#include <cstdint>

#define BDIM 2048
#define PDIM 4096
#define PD_TP 4086
#define CONS 10
#define QDIM 1024
#define ND 192          // Wcat columns: [0,64)=cw1, [64,192)=ow1[:P]
#define SK2 200         // padded k-stride (elems)
#define SKA 40          // gemm1 smem k-stride (elems)
#define NSPLIT 16       // gemm1 split-K
#define FR 16           // finish3 rows per block

// ---------------- device scratch (allocation-free) ----------------
__device__ __align__(256) float          g_m[PDIM];
__device__ __align__(256) float          g_G[ND * ND];                        // Gram Wcat^T Wcat
__device__ __align__(256) float          g_params[(size_t)BDIM * PDIM];       // params0 fp32
__device__ __align__(256) __nv_bfloat16  g_pbf[(size_t)BDIM * PDIM];          // params0 bf16
__device__ __align__(256) __nv_bfloat16  g_WAt[(size_t)ND * PDIM];            // Wcat^T [n][k]
__device__ __align__(256) __nv_bfloat16  g_WBt[(size_t)PDIM * SK2];           // Wcat   [p][n pad]
__device__ __align__(256) float          g_accp[(size_t)NSPLIT * BDIM * ND];  // gemm1 partials
__device__ __align__(256) __nv_bfloat16  g_dcat[(size_t)BDIM * SK2];          // final D bf16

// ---------------- helpers ----------------
__device__ __forceinline__ void cp16(void* s, const void* g) {
    uint32_t sa = (uint32_t)__cvta_generic_to_shared(s);
    asm volatile("cp.async.cg.shared.global [%0], [%1], 16;\n" :: "r"(sa), "l"(g));
}
__device__ __forceinline__ void cp_commit() { asm volatile("cp.async.commit_group;\n"); }
__device__ __forceinline__ void cp_wait0()  { asm volatile("cp.async.wait_group 0;\n"); }
__device__ __forceinline__ void cp_wait1()  { asm volatile("cp.async.wait_group 1;\n"); }

__device__ __forceinline__ void mma_bf16(float* c, const uint32_t* a, const uint32_t* b) {
    asm volatile(
        "mma.sync.aligned.m16n8k16.row.col.f32.bf16.bf16.f32 "
        "{%0,%1,%2,%3},{%4,%5,%6,%7},{%8,%9},{%0,%1,%2,%3};\n"
        : "+f"(c[0]), "+f"(c[1]), "+f"(c[2]), "+f"(c[3])
        : "r"(a[0]), "r"(a[1]), "r"(a[2]), "r"(a[3]), "r"(b[0]), "r"(b[1]));
}
__device__ __forceinline__ void ldsm4(uint32_t& r0, uint32_t& r1, uint32_t& r2, uint32_t& r3,
                                      const void* p) {
    uint32_t a = (uint32_t)__cvta_generic_to_shared(p);
    asm volatile("ldmatrix.sync.aligned.m8n8.x4.shared.b16 {%0,%1,%2,%3},[%4];\n"
                 : "=r"(r0), "=r"(r1), "=r"(r2), "=r"(r3) : "r"(a));
}
__device__ __forceinline__ float ftanh(float x) {
    float y; asm("tanh.approx.f32 %0, %1;\n" : "=f"(y) : "f"(x)); return y;
}

// ---------------- k_setup: colmean + gram + WAt-transpose + WBt ----------------
#define NB_CM   128
#define NB_GRAM 36
#define NB_WAT  64
#define NB_WBT  3200
__global__ void __launch_bounds__(256) k_setup(const float* __restrict__ mp,
                                               const float* __restrict__ cw1,
                                               const float* __restrict__ ow1) {
    __shared__ __align__(16) char sraw[28672];
    const int blk = blockIdx.x, tid = threadIdx.x;

    if (blk < NB_CM) {
        float* sbuf = (float*)sraw;
        int p = blk * 32 + (tid & 31);
        int qi = tid >> 5;
        float s = 0.f;
        #pragma unroll 8
        for (int q = qi * 128; q < qi * 128 + 128; q++)
            s += mp[(size_t)q * PDIM + p];
        sbuf[qi * 32 + (tid & 31)] = s;
        __syncthreads();
        if (tid < 32) {
            float t = 0.f;
            #pragma unroll
            for (int r = 0; r < 8; r++) t += sbuf[r * 32 + tid];
            g_m[blk * 32 + tid] = t * (1.0f / QDIM);
        }
        return;
    }

    if (blk < NB_CM + NB_GRAM) {
        float* sA = (float*)sraw;          // 64 x 32
        float* sB = sA + 2048;             // 64 x 32
        int gb = blk - NB_CM;
        int i0 = (gb / 6) * 32, j0 = (gb % 6) * 32;
        int tx = tid & 15, ty = tid >> 4;
        float c00 = 0.f, c01 = 0.f, c10 = 0.f, c11 = 0.f;
        for (int kc = 0; kc < 64; kc++) {
            int kb = kc * 64;
            #pragma unroll
            for (int r = 0; r < 8; r++) {
                int idx = tid + r * 256;
                int kk = idx >> 5, cc = idx & 31;
                int ci = i0 + cc, cj = j0 + cc, k = kb + kk;
                sA[kk * 32 + cc] = (ci < 64) ? cw1[k * 64 + ci] : ow1[k * 128 + ci - 64];
                sB[kk * 32 + cc] = (cj < 64) ? cw1[k * 64 + cj] : ow1[k * 128 + cj - 64];
            }
            __syncthreads();
            #pragma unroll 8
            for (int k = 0; k < 64; k++) {
                float a0 = sA[k * 32 + 2 * tx], a1 = sA[k * 32 + 2 * tx + 1];
                float b0 = sB[k * 32 + 2 * ty], b1 = sB[k * 32 + 2 * ty + 1];
                c00 += a0 * b0; c01 += a0 * b1;
                c10 += a1 * b0; c11 += a1 * b1;
            }
            __syncthreads();
        }
        int gi = i0 + 2 * tx, gj = j0 + 2 * ty;
        g_G[gi * ND + gj]           = c00;
        g_G[gi * ND + gj + 1]       = c01;
        g_G[(gi + 1) * ND + gj]     = c10;
        g_G[(gi + 1) * ND + gj + 1] = c11;
        return;
    }

    if (blk < NB_CM + NB_GRAM + NB_WAT) {
        // WAt transpose tile: 64 k-columns per block, coalesced reads + writes
        __nv_bfloat16* st = (__nv_bfloat16*)sraw;   // [192][72]
        int k0 = (blk - NB_CM - NB_GRAM) * 64;
        for (int i = tid; i < 4096; i += 256) {     // cw1: 64k x 64n
            int kk = i >> 6, ci = i & 63;
            st[ci * 72 + kk] = __float2bfloat16(cw1[(size_t)(k0 + kk) * 64 + ci]);
        }
        for (int i = tid; i < 8192; i += 256) {     // ow1: 64k x 128n
            int kk = i >> 7, cj = i & 127;
            st[(64 + cj) * 72 + kk] = __float2bfloat16(ow1[(size_t)(k0 + kk) * 128 + cj]);
        }
        __syncthreads();
        for (int i = tid; i < 3072; i += 256) {     // write 192n x 64k as uint2
            int n = i >> 4, k4 = (i & 15) * 4;
            uint2 v = *(const uint2*)&st[n * 72 + k4];
            *(uint2*)&g_WAt[(size_t)n * PDIM + k0 + k4] = v;
        }
        return;
    }

    // WBt: coalesced both sides
    int j = (blk - NB_CM - NB_GRAM - NB_WAT) * 256 + tid;
    int p = j / SK2, q = j % SK2;
    float v = 0.f;
    if (q < 64)       v = cw1[p * 64 + q];
    else if (q < ND)  v = ow1[p * 128 + (q - 64)];
    g_WBt[j] = __float2bfloat16(v);
}

// ---------------- params0 = tanh(0.7*colmean + 0.3*enc) ----------------
__global__ void __launch_bounds__(256) k_init(const float* __restrict__ tp,
                                              const float* __restrict__ cons) {
    int idx = blockIdx.x * 256 + threadIdx.x;
    int b = idx >> 10;
    int pg = (idx & 1023) << 2;
    const float* trow = tp + (size_t)b * PD_TP;
    float e0, e1, e2, e3;
    if (pg + 3 < PD_TP) {
        float2 u = *(const float2*)(trow + pg);
        float2 v2 = *(const float2*)(trow + pg + 2);
        e0 = u.x; e1 = u.y; e2 = v2.x; e3 = v2.y;
    } else if (pg < PD_TP) {
        float2 u = *(const float2*)(trow + pg);
        e0 = u.x; e1 = u.y;
        e2 = cons[b * CONS + 0]; e3 = cons[b * CONS + 1];
    } else {
        int c0 = pg - PD_TP;
        e0 = cons[b * CONS + c0];     e1 = cons[b * CONS + c0 + 1];
        e2 = cons[b * CONS + c0 + 2]; e3 = cons[b * CONS + c0 + 3];
    }
    float4 m4 = *(const float4*)&g_m[pg];
    float v0 = ftanh(0.7f * m4.x + 0.3f * e0);
    float v1 = ftanh(0.7f * m4.y + 0.3f * e1);
    float v2_ = ftanh(0.7f * m4.z + 0.3f * e2);
    float v3 = ftanh(0.7f * m4.w + 0.3f * e3);
    size_t o = (size_t)b * PDIM + pg;
    *(float4*)&g_params[o] = make_float4(v0, v1, v2_, v3);
    union { __nv_bfloat162 h[2]; uint2 u; } pk;
    pk.h[0] = __floats2bfloat162_rn(v0, v1);
    pk.h[1] = __floats2bfloat162_rn(v2_, v3);
    *(uint2*)&g_pbf[o] = pk.u;
}

// ---------------- GEMM1: accp = pbf x WAt^T, split-K=16, 3-stage ring ----------------
__global__ void __launch_bounds__(256, 2) k_gemm1() {
    extern __shared__ char smem_raw[];
    __nv_bfloat16* smem = (__nv_bfloat16*)smem_raw;
    const int STG_E = 128 * SKA + ND * SKA;
    const int tid = threadIdx.x, lane = tid & 31, w = tid >> 5;
    const int wm = w >> 1, wn = w & 1, g = lane >> 2, tg = lane & 3;
    const int m0 = blockIdx.x * 128;
    const int ks0 = blockIdx.y * 256;

    float acc[2][12][4];
    #pragma unroll
    for (int i = 0; i < 2; i++)
        #pragma unroll
        for (int j = 0; j < 12; j++)
            #pragma unroll
            for (int q = 0; q < 4; q++) acc[i][j][q] = 0.f;

    auto load_stage = [&](int st, int kt) {
        __nv_bfloat16* sA = smem + st * STG_E;
        __nv_bfloat16* sB = sA + 128 * SKA;
        #pragma unroll
        for (int i = 0; i < 2; i++) {
            int idx = tid + i * 256;
            int row = idx >> 2, ch = idx & 3;
            cp16(&sA[row * SKA + ch * 8], &g_pbf[(size_t)(m0 + row) * PDIM + kt + ch * 8]);
        }
        #pragma unroll
        for (int i = 0; i < 3; i++) {
            int idx = tid + i * 256;
            int row = idx >> 2, ch = idx & 3;
            cp16(&sB[row * SKA + ch * 8], &g_WAt[(size_t)row * PDIM + kt + ch * 8]);
        }
        cp_commit();
    };

    load_stage(0, ks0);
    load_stage(1, ks0 + 32);

    const int arow = lane & 15, asel = (lane >> 4) << 3;
    const int brow = (lane & 7) + ((lane >> 4) << 3), bsel = ((lane >> 3) & 1) << 3;

    for (int it = 0; it < 8; it++) {
        if (it < 7) cp_wait1(); else cp_wait0();
        __syncthreads();
        if (it + 2 < 8) load_stage((it + 2) % 3, ks0 + (it + 2) * 32);

        __nv_bfloat16* sA = smem + (it % 3) * STG_E;
        __nv_bfloat16* sB = sA + 128 * SKA;
        #pragma unroll
        for (int ks = 0; ks < 32; ks += 16) {
            uint32_t a[2][4];
            #pragma unroll
            for (int mf = 0; mf < 2; mf++)
                ldsm4(a[mf][0], a[mf][1], a[mf][2], a[mf][3],
                      &sA[(wm * 32 + mf * 16 + arow) * SKA + ks + asel]);
            #pragma unroll
            for (int nt = 0; nt < 6; nt++) {
                uint32_t b0, b1, b2, b3;
                ldsm4(b0, b1, b2, b3,
                      &sB[(wn * 96 + nt * 16 + brow) * SKA + ks + bsel]);
                uint32_t bp0[2] = {b0, b1}, bp1[2] = {b2, b3};
                #pragma unroll
                for (int mf = 0; mf < 2; mf++) {
                    mma_bf16(acc[mf][nt * 2],     a[mf], bp0);
                    mma_bf16(acc[mf][nt * 2 + 1], a[mf], bp1);
                }
            }
        }
        __syncthreads();
    }

    float* out = &g_accp[(size_t)blockIdx.y * BDIM * ND];
    #pragma unroll
    for (int mf = 0; mf < 2; mf++)
        #pragma unroll
        for (int nf = 0; nf < 12; nf++) {
            int r = m0 + wm * 32 + mf * 16 + g;
            int c = wn * 96 + nf * 8 + tg * 2;
            *(float2*)&out[(size_t)r * ND + c]       = make_float2(acc[mf][nf][0], acc[mf][nf][1]);
            *(float2*)&out[(size_t)(r + 8) * ND + c] = make_float2(acc[mf][nf][2], acc[mf][nf][3]);
        }
}

// ---------------- k_finish3: 3 steps, 16 rows/block, 512 threads, mma ds@G ----------------
#define SMEMF 181824
__global__ void __launch_bounds__(512) k_finish3(
    const float* __restrict__ cb1, const float* __restrict__ cw2,
    const float* __restrict__ cb2, const float* __restrict__ ow1,
    const float* __restrict__ ob1, const float* __restrict__ ow2,
    const float* __restrict__ ob2, const float* __restrict__ ow3) {
    extern __shared__ char sm[];
    char* p = sm;
    __nv_bfloat16* sG   = (__nv_bfloat16*)p; p += 192 * 200 * 2;   // [192][200]
    __nv_bfloat16* sdsb = (__nv_bfloat16*)p; p += 16 * 200 * 2;    // [16][200]
    float* sW2  = (float*)p; p += 128 * 68 * 4;                    // ow2 padded
    float* sW1c = (float*)p; p += 1280 * 4;                        // ow1[P:] [10][128]
    float* sCw2 = (float*)p; p += 640 * 4;
    float* sb   = (float*)p; p += 336 * 4;                         // cb1|cb2|ob1|ob2|ow3
    float* sacc = (float*)p; p += FR * 192 * 4;
    float* sds  = (float*)p; p += FR * 192 * 4;
    float* sD   = (float*)p; p += FR * 192 * 4;
    float* sh1c = (float*)p; p += FR * 64 * 4;
    float* scv  = (float*)p; p += FR * 12 * 4;
    float* sdzc = (float*)p; p += FR * 12 * 4;
    float* sa1  = (float*)p; p += FR * 128 * 4;
    float* sdz2 = (float*)p;

    const int tid = threadIdx.x, lane = tid & 31, w = tid >> 5;
    const int b0 = blockIdx.x * FR;

    // ---- weights once ----
    for (int i = tid; i < 192 * 96; i += 512) {        // G -> bf16, stride 200
        int m = i / 96, n2 = i % 96;
        float2 v = *(const float2*)&g_G[m * 192 + n2 * 2];
        ((__nv_bfloat162*)sG)[m * 100 + n2] = __floats2bfloat162_rn(v.x, v.y);
    }
    for (int i = tid; i < 8192; i += 512) {
        int j = i >> 6, k = i & 63;
        sW2[j * 68 + k] = ow2[i];
    }
    for (int i = tid; i < 1280; i += 512) {
        int q = i >> 7, j = i & 127;
        sW1c[i] = ow1[(PDIM + q) * 128 + j];
    }
    for (int i = tid; i < 640; i += 512) sCw2[i] = cw2[i];
    if (tid < 64)  sb[tid]       = cb1[tid];
    if (tid < 10)  sb[64 + tid]  = cb2[tid];
    if (tid < 128) sb[80 + tid]  = ob1[tid];
    if (tid < 64)  sb[208 + tid] = ob2[tid];
    if (tid < 64)  sb[272 + tid] = ow3[tid];

    // ---- acc0 = sum of split-K partials; D = 0 ----
    for (int i = tid; i < FR * 48; i += 512) {
        int r = i / 48, n4 = (i % 48) * 4;
        size_t bb = (size_t)(b0 + r);
        float4 s = make_float4(0.f, 0.f, 0.f, 0.f);
        #pragma unroll
        for (int sp = 0; sp < NSPLIT; sp++) {
            float4 v = *(const float4*)&g_accp[((size_t)sp * BDIM + bb) * ND + n4];
            s.x += v.x; s.y += v.y; s.z += v.z; s.w += v.w;
        }
        *(float4*)&sacc[r * 192 + n4] = s;
    }
    for (int i = tid; i < FR * 192; i += 512) sD[i] = 0.f;
    __syncthreads();

    for (int step = 0; step < 3; step++) {
        // h1c = relu(acc[:64] + cb1)
        for (int i = tid; i < FR * 64; i += 512) {
            int r = i >> 6, j = i & 63;
            sh1c[i] = fmaxf(sacc[r * 192 + j] + sb[j], 0.f);
        }
        __syncthreads();
        // cv = sigmoid(h1c @ cw2 + cb2)
        if (tid < FR * 10) {
            int r = tid / 10, q = tid % 10;
            float s = sb[64 + q];
            #pragma unroll 8
            for (int k = 0; k < 64; k++) s += sh1c[r * 64 + k] * sCw2[k * 10 + q];
            scv[r * 12 + q] = 1.f / (1.f + expf(-s));
        }
        __syncthreads();
        // a1 = relu(acc[64:] + ob1 + cv @ ow1[P:])
        for (int i = tid; i < FR * 128; i += 512) {
            int r = i >> 7, j = i & 127;
            float z = sacc[r * 192 + 64 + j] + sb[80 + j];
            #pragma unroll
            for (int q = 0; q < 10; q++) z += scv[r * 12 + q] * sW1c[q * 128 + j];
            sa1[i] = fmaxf(z, 0.f);
        }
        __syncthreads();
        // dz2 = relu'(a1 @ ow2 + ob2) * ow3
        {
            int r = tid >> 5, kp = tid & 31;
            int k2 = kp * 2;
            float s0 = sb[208 + k2], s1 = sb[208 + k2 + 1];
            const float* a1r = &sa1[r * 128];
            #pragma unroll 8
            for (int j = 0; j < 128; j++) {
                float a = a1r[j];
                float2 wv = *(const float2*)&sW2[j * 68 + k2];
                s0 += a * wv.x; s1 += a * wv.y;
            }
            sdz2[r * 64 + k2]     = (s0 > 0.f) ? sb[272 + k2] : 0.f;
            sdz2[r * 64 + k2 + 1] = (s1 > 0.f) ? sb[272 + k2 + 1] : 0.f;
        }
        __syncthreads();
        // dz1 (scaled -0.01) -> sds[64+j]
        for (int s4 = 0; s4 < 4; s4++) {
            int i = tid + s4 * 512;
            int r = i >> 7, j = i & 127;
            const float* dzr = &sdz2[r * 64];
            const float* wr = &sW2[j * 68];
            float s = 0.f;
            #pragma unroll
            for (int k = 0; k < 64; k += 4) {
                float4 dv = *(const float4*)&dzr[k];
                float4 wv = *(const float4*)&wr[k];
                s += dv.x * wv.x + dv.y * wv.y + dv.z * wv.z + dv.w * wv.w;
            }
            sds[r * 192 + 64 + j] = (sa1[i] > 0.f) ? -0.01f * s : 0.f;
        }
        __syncthreads();
        // dzc = (dz1 @ ow1c^T) * cv*(1-cv)
        if (tid < FR * 10) {
            int r = tid / 10, q = tid % 10;
            const float* dsr = &sds[r * 192 + 64];
            const float* wr = &sW1c[q * 128];
            float s = 0.f;
            #pragma unroll
            for (int j = 0; j < 128; j += 4) {
                float4 dv = *(const float4*)&dsr[j];
                float4 wv = *(const float4*)&wr[j];
                s += dv.x * wv.x + dv.y * wv.y + dv.z * wv.z + dv.w * wv.w;
            }
            float c = scv[r * 12 + q];
            sdzc[r * 12 + q] = s * c * (1.f - c);
        }
        __syncthreads();
        // dconstr -> sds[0..64)
        for (int i = tid; i < FR * 64; i += 512) {
            int r = i >> 6, j = i & 63;
            float s = 0.f;
            #pragma unroll
            for (int q = 0; q < 10; q++) s += sdzc[r * 12 + q] * sCw2[j * 10 + q];
            sds[r * 192 + j] = (sacc[r * 192 + j] + sb[j] > 0.f) ? s : 0.f;
        }
        __syncthreads();
        // D += ds
        for (int i = tid; i < FR * 192; i += 512) sD[i] += sds[i];

        if (step < 2) {
            // ds -> bf16 (stride 200)
            for (int i = tid; i < FR * 96; i += 512) {
                int r = i / 96, n2 = i % 96;
                float2 v = *(const float2*)&sds[r * 192 + n2 * 2];
                ((__nv_bfloat162*)sdsb)[r * 100 + n2] = __floats2bfloat162_rn(v.x, v.y);
            }
            __syncthreads();
            // acc += ds @ G via mma (G symmetric -> B[n][k] = G[n][k])
            if (w < 12) {
                int n0 = w * 16;
                float c[2][4] = {{0.f,0.f,0.f,0.f},{0.f,0.f,0.f,0.f}};
                const int arow = lane & 15, asel = (lane >> 4) << 3;
                const int brow = (lane & 7) + ((lane >> 4) << 3), bsel = ((lane >> 3) & 1) << 3;
                #pragma unroll
                for (int ks = 0; ks < 192; ks += 16) {
                    uint32_t a[4];
                    ldsm4(a[0], a[1], a[2], a[3], &sdsb[arow * 200 + ks + asel]);
                    uint32_t b0, b1, b2, b3;
                    ldsm4(b0, b1, b2, b3, &sG[(n0 + brow) * 200 + ks + bsel]);
                    uint32_t bp0[2] = {b0, b1}, bp1[2] = {b2, b3};
                    mma_bf16(c[0], a, bp0);
                    mma_bf16(c[1], a, bp1);
                }
                int g = lane >> 2, tg = lane & 3;
                #pragma unroll
                for (int nt = 0; nt < 2; nt++) {
                    int col = n0 + nt * 8 + tg * 2;
                    sacc[g * 192 + col]           += c[nt][0];
                    sacc[g * 192 + col + 1]       += c[nt][1];
                    sacc[(g + 8) * 192 + col]     += c[nt][2];
                    sacc[(g + 8) * 192 + col + 1] += c[nt][3];
                }
            }
        }
        __syncthreads();
    }

    // write dcat (bf16, padded to SK2)
    for (int i = tid; i < FR * SK2; i += 512) {
        int r = i / SK2, n = i % SK2;
        g_dcat[(size_t)(b0 + r) * SK2 + n] =
            __float2bfloat16(n < 192 ? sD[r * 192 + n] : 0.f);
    }
}

// ---------------- GEMM2: out = params0 + D x Wcat^T, n-tile 64 ----------------
__global__ void __launch_bounds__(256, 2) k_gemm2(float* __restrict__ outp) {
    extern __shared__ char smem_raw[];
    __nv_bfloat16* sA = (__nv_bfloat16*)smem_raw;          // 128 x 200
    __nv_bfloat16* sB = sA + 128 * SK2;                    // 64 x 200
    const int tid = threadIdx.x, lane = tid & 31, w = tid >> 5;
    const int wm = w >> 1, wn = w & 1, g = lane >> 2, tg = lane & 3;
    const int m0 = blockIdx.x * 128;
    const int n0 = blockIdx.y * 64;

    #pragma unroll
    for (int i = 0; i < 12; i++) {
        int idx = tid + i * 256;
        int row = idx / 24, ch = idx % 24;
        cp16(&sA[row * SK2 + ch * 8], &g_dcat[(size_t)(m0 + row) * SK2 + ch * 8]);
    }
    for (int idx = tid; idx < 1600; idx += 256) {
        int row = idx / 25, ch = idx % 25;
        if (ch < 24)
            cp16(&sB[row * SK2 + ch * 8], &g_WBt[(size_t)(n0 + row) * SK2 + ch * 8]);
    }
    cp_commit();

    float acc[2][4][4];
    #pragma unroll
    for (int i = 0; i < 2; i++)
        #pragma unroll
        for (int j = 0; j < 4; j++)
            #pragma unroll
            for (int q = 0; q < 4; q++) acc[i][j][q] = 0.f;

    cp_wait0();
    __syncthreads();

    const int arow = lane & 15, asel = (lane >> 4) << 3;
    const int brow = (lane & 7) + ((lane >> 4) << 3), bsel = ((lane >> 3) & 1) << 3;

    #pragma unroll
    for (int ks = 0; ks < ND; ks += 16) {
        uint32_t a[2][4];
        #pragma unroll
        for (int mf = 0; mf < 2; mf++)
            ldsm4(a[mf][0], a[mf][1], a[mf][2], a[mf][3],
                  &sA[(wm * 32 + mf * 16 + arow) * SK2 + ks + asel]);
        #pragma unroll
        for (int nt = 0; nt < 2; nt++) {
            uint32_t b0, b1, b2, b3;
            ldsm4(b0, b1, b2, b3,
                  &sB[(wn * 32 + nt * 16 + brow) * SK2 + ks + bsel]);
            uint32_t bp0[2] = {b0, b1}, bp1[2] = {b2, b3};
            #pragma unroll
            for (int mf = 0; mf < 2; mf++) {
                mma_bf16(acc[mf][nt * 2],     a[mf], bp0);
                mma_bf16(acc[mf][nt * 2 + 1], a[mf], bp1);
            }
        }
    }

    #pragma unroll
    for (int mf = 0; mf < 2; mf++)
        #pragma unroll
        for (int nf = 0; nf < 4; nf++) {
            int r = m0 + wm * 32 + mf * 16 + g;
            int c = n0 + wn * 32 + nf * 8 + tg * 2;
            size_t i0 = (size_t)r * PDIM + c;
            size_t i1 = i0 + (size_t)8 * PDIM;
            float2 pv0 = *(const float2*)&g_params[i0];
            float2 pv1 = *(const float2*)&g_params[i1];
            *(float2*)&outp[i0] = make_float2(pv0.x + acc[mf][nf][0], pv0.y + acc[mf][nf][1]);
            *(float2*)&outp[i1] = make_float2(pv1.x + acc[mf][nf][2], pv1.y + acc[mf][nf][3]);
        }
}

// ---------------- launch ----------------
extern "C" void kernel_launch(void* const* d_in, const int* in_sizes, int n_in,
                              void* d_out, int out_size) {
    const float* tp   = (const float*)d_in[0];
    const float* cons = (const float*)d_in[1];
    // d_in[2] transverse_field, d_in[3] coupling, d_in[14] ob3 : dead
    const float* mp   = (const float*)d_in[4];
    const float* cw1  = (const float*)d_in[5];
    const float* cb1  = (const float*)d_in[6];
    const float* cw2  = (const float*)d_in[7];
    const float* cb2  = (const float*)d_in[8];
    const float* ow1  = (const float*)d_in[9];
    const float* ob1  = (const float*)d_in[10];
    const float* ow2  = (const float*)d_in[11];
    const float* ob2  = (const float*)d_in[12];
    const float* ow3  = (const float*)d_in[13];
    float* outp = (float*)d_out;

    const int SMEM1 = 3 * (128 * SKA + ND * SKA) * 2;   // 76800
    const int SMEM2 = (128 * SK2 + 64 * SK2) * 2;       // 76800
    cudaFuncSetAttribute(k_gemm1,   cudaFuncAttributeMaxDynamicSharedMemorySize, SMEM1);
    cudaFuncSetAttribute(k_gemm2,   cudaFuncAttributeMaxDynamicSharedMemorySize, SMEM2);
    cudaFuncSetAttribute(k_finish3, cudaFuncAttributeMaxDynamicSharedMemorySize, SMEMF);

    k_setup<<<NB_CM + NB_GRAM + NB_WAT + NB_WBT, 256>>>(mp, cw1, ow1);
    k_init<<<(BDIM * PDIM / 4) / 256, 256>>>(tp, cons);
    k_gemm1<<<dim3(16, NSPLIT), 256, SMEM1>>>();
    k_finish3<<<BDIM / FR, 512, SMEMF>>>(cb1, cw2, cb2, ow1, ob1, ow2, ob2, ow3);
    k_gemm2<<<dim3(16, 64), 256, SMEM2>>>(outp);
}

// round 8
// speedup vs baseline: 1.2226x; 1.2226x over previous
#include <cuda_runtime.h>
#include <cuda_bf16.h>
#include <cstdint>

#define BDIM 2048
#define PDIM 4096
#define PD_TP 4086
#define CONS 10
#define QDIM 1024
#define ND 192          // Wcat columns: [0,64)=cw1, [64,192)=ow1[:P]
#define SK2 200         // padded k-stride (elems)
#define SKA 40          // gemm1 smem k-stride (elems)
#define NSPLIT 16       // gemm1 split-K
#define FR 16           // finish3 rows per block

// ---------------- device scratch (allocation-free) ----------------
__device__ __align__(256) float          g_m[PDIM];
__device__ __align__(256) float          g_G[ND * ND];                        // Gram Wcat^T Wcat
__device__ __align__(256) float          g_params[(size_t)BDIM * PDIM];       // params0 fp32
__device__ __align__(256) __nv_bfloat16  g_pbf[(size_t)BDIM * PDIM];          // params0 bf16
__device__ __align__(256) __nv_bfloat16  g_WAt[(size_t)ND * PDIM];            // Wcat^T [n][k]
__device__ __align__(256) __nv_bfloat16  g_WBt[(size_t)PDIM * SK2];           // Wcat   [p][n pad]
__device__ __align__(256) float          g_accp[(size_t)NSPLIT * BDIM * ND];  // gemm1 partials
__device__ __align__(256) __nv_bfloat16  g_dcat[(size_t)BDIM * SK2];          // final D bf16

// ---------------- helpers ----------------
__device__ __forceinline__ void cp16(void* s, const void* g) {
    uint32_t sa = (uint32_t)__cvta_generic_to_shared(s);
    asm volatile("cp.async.cg.shared.global [%0], [%1], 16;\n" :: "r"(sa), "l"(g));
}
__device__ __forceinline__ void cp_commit() { asm volatile("cp.async.commit_group;\n"); }
__device__ __forceinline__ void cp_wait0()  { asm volatile("cp.async.wait_group 0;\n"); }
__device__ __forceinline__ void cp_wait1()  { asm volatile("cp.async.wait_group 1;\n"); }

__device__ __forceinline__ void mma_bf16(float* c, const uint32_t* a, const uint32_t* b) {
    asm volatile(
        "mma.sync.aligned.m16n8k16.row.col.f32.bf16.bf16.f32 "
        "{%0,%1,%2,%3},{%4,%5,%6,%7},{%8,%9},{%0,%1,%2,%3};\n"
        : "+f"(c[0]), "+f"(c[1]), "+f"(c[2]), "+f"(c[3])
        : "r"(a[0]), "r"(a[1]), "r"(a[2]), "r"(a[3]), "r"(b[0]), "r"(b[1]));
}
__device__ __forceinline__ void ldsm4(uint32_t& r0, uint32_t& r1, uint32_t& r2, uint32_t& r3,
                                      const void* p) {
    uint32_t a = (uint32_t)__cvta_generic_to_shared(p);
    asm volatile("ldmatrix.sync.aligned.m8n8.x4.shared.b16 {%0,%1,%2,%3},[%4];\n"
                 : "=r"(r0), "=r"(r1), "=r"(r2), "=r"(r3) : "r"(a));
}
__device__ __forceinline__ float ftanh(float x) {
    float y; asm("tanh.approx.f32 %0, %1;\n" : "=f"(y) : "f"(x)); return y;
}

// ---------------- k_setup: colmean + gram + prepw (R5-measured structure) ----------------
#define NB_CM   128
#define NB_GRAM 36
#define NB_PREP 6272
__global__ void __launch_bounds__(256) k_setup(const float* __restrict__ mp,
                                               const float* __restrict__ cw1,
                                               const float* __restrict__ ow1) {
    __shared__ float sbuf[4096];
    const int blk = blockIdx.x, tid = threadIdx.x;

    if (blk < NB_CM) {
        int p = blk * 32 + (tid & 31);
        int qi = tid >> 5;
        float s = 0.f;
        #pragma unroll 8
        for (int q = qi * 128; q < qi * 128 + 128; q++)
            s += mp[(size_t)q * PDIM + p];
        sbuf[qi * 32 + (tid & 31)] = s;
        __syncthreads();
        if (tid < 32) {
            float t = 0.f;
            #pragma unroll
            for (int r = 0; r < 8; r++) t += sbuf[r * 32 + tid];
            g_m[blk * 32 + tid] = t * (1.0f / QDIM);
        }
        return;
    }

    if (blk < NB_CM + NB_GRAM) {
        float* sA = sbuf;
        float* sB = sbuf + 2048;
        int gb = blk - NB_CM;
        int i0 = (gb / 6) * 32, j0 = (gb % 6) * 32;
        int tx = tid & 15, ty = tid >> 4;
        float c00 = 0.f, c01 = 0.f, c10 = 0.f, c11 = 0.f;
        for (int kc = 0; kc < 64; kc++) {
            int kb = kc * 64;
            #pragma unroll
            for (int r = 0; r < 8; r++) {
                int idx = tid + r * 256;
                int kk = idx >> 5, cc = idx & 31;
                int ci = i0 + cc, cj = j0 + cc, k = kb + kk;
                sA[kk * 32 + cc] = (ci < 64) ? cw1[k * 64 + ci] : ow1[k * 128 + ci - 64];
                sB[kk * 32 + cc] = (cj < 64) ? cw1[k * 64 + cj] : ow1[k * 128 + cj - 64];
            }
            __syncthreads();
            #pragma unroll 8
            for (int k = 0; k < 64; k++) {
                float a0 = sA[k * 32 + 2 * tx], a1 = sA[k * 32 + 2 * tx + 1];
                float b0 = sB[k * 32 + 2 * ty], b1 = sB[k * 32 + 2 * ty + 1];
                c00 += a0 * b0; c01 += a0 * b1;
                c10 += a1 * b0; c11 += a1 * b1;
            }
            __syncthreads();
        }
        int gi = i0 + 2 * tx, gj = j0 + 2 * ty;
        g_G[gi * ND + gj]           = c00;
        g_G[gi * ND + gj + 1]       = c01;
        g_G[(gi + 1) * ND + gj]     = c10;
        g_G[(gi + 1) * ND + gj + 1] = c11;
        return;
    }

    // prepw (R3-measured 8.9us): WAt [n][k] + WBt [p][n pad]
    int idx = (blk - NB_CM - NB_GRAM) * 256 + tid;
    const int T1 = ND * PDIM;       // 786432
    if (idx < T1) {
        int n = idx / PDIM, k = idx % PDIM;
        float v = (n < 64) ? cw1[k * 64 + n] : ow1[k * 128 + (n - 64)];
        g_WAt[idx] = __float2bfloat16(v);
    } else {
        int j = idx - T1;           // PDIM*SK2 = 819200
        int p = j / SK2, q = j % SK2;
        float v = 0.f;
        if (q < 64)       v = cw1[p * 64 + q];
        else if (q < ND)  v = ow1[p * 128 + (q - 64)];
        g_WBt[j] = __float2bfloat16(v);
    }
}

// ---------------- params0 = tanh(0.7*colmean + 0.3*enc) ----------------
__global__ void __launch_bounds__(256) k_init(const float* __restrict__ tp,
                                              const float* __restrict__ cons) {
    int idx = blockIdx.x * 256 + threadIdx.x;
    int b = idx >> 10;
    int pg = (idx & 1023) << 2;
    const float* trow = tp + (size_t)b * PD_TP;
    float e0, e1, e2, e3;
    if (pg + 3 < PD_TP) {
        float2 u = *(const float2*)(trow + pg);
        float2 v2 = *(const float2*)(trow + pg + 2);
        e0 = u.x; e1 = u.y; e2 = v2.x; e3 = v2.y;
    } else if (pg < PD_TP) {
        float2 u = *(const float2*)(trow + pg);
        e0 = u.x; e1 = u.y;
        e2 = cons[b * CONS + 0]; e3 = cons[b * CONS + 1];
    } else {
        int c0 = pg - PD_TP;
        e0 = cons[b * CONS + c0];     e1 = cons[b * CONS + c0 + 1];
        e2 = cons[b * CONS + c0 + 2]; e3 = cons[b * CONS + c0 + 3];
    }
    float4 m4 = *(const float4*)&g_m[pg];
    float v0 = ftanh(0.7f * m4.x + 0.3f * e0);
    float v1 = ftanh(0.7f * m4.y + 0.3f * e1);
    float v2_ = ftanh(0.7f * m4.z + 0.3f * e2);
    float v3 = ftanh(0.7f * m4.w + 0.3f * e3);
    size_t o = (size_t)b * PDIM + pg;
    *(float4*)&g_params[o] = make_float4(v0, v1, v2_, v3);
    union { __nv_bfloat162 h[2]; uint2 u; } pk;
    pk.h[0] = __floats2bfloat162_rn(v0, v1);
    pk.h[1] = __floats2bfloat162_rn(v2_, v3);
    *(uint2*)&g_pbf[o] = pk.u;
}

// ---------------- GEMM1: accp = pbf x WAt^T, split-K=16, 3-stage ring ----------------
__global__ void __launch_bounds__(256, 2) k_gemm1() {
    extern __shared__ char smem_raw[];
    __nv_bfloat16* smem = (__nv_bfloat16*)smem_raw;
    const int STG_E = 128 * SKA + ND * SKA;
    const int tid = threadIdx.x, lane = tid & 31, w = tid >> 5;
    const int wm = w >> 1, wn = w & 1, g = lane >> 2, tg = lane & 3;
    const int m0 = blockIdx.x * 128;
    const int ks0 = blockIdx.y * 256;

    float acc[2][12][4];
    #pragma unroll
    for (int i = 0; i < 2; i++)
        #pragma unroll
        for (int j = 0; j < 12; j++)
            #pragma unroll
            for (int q = 0; q < 4; q++) acc[i][j][q] = 0.f;

    auto load_stage = [&](int st, int kt) {
        __nv_bfloat16* sA = smem + st * STG_E;
        __nv_bfloat16* sB = sA + 128 * SKA;
        #pragma unroll
        for (int i = 0; i < 2; i++) {
            int idx = tid + i * 256;
            int row = idx >> 2, ch = idx & 3;
            cp16(&sA[row * SKA + ch * 8], &g_pbf[(size_t)(m0 + row) * PDIM + kt + ch * 8]);
        }
        #pragma unroll
        for (int i = 0; i < 3; i++) {
            int idx = tid + i * 256;
            int row = idx >> 2, ch = idx & 3;
            cp16(&sB[row * SKA + ch * 8], &g_WAt[(size_t)row * PDIM + kt + ch * 8]);
        }
        cp_commit();
    };

    load_stage(0, ks0);
    load_stage(1, ks0 + 32);

    const int arow = lane & 15, asel = (lane >> 4) << 3;
    const int brow = (lane & 7) + ((lane >> 4) << 3), bsel = ((lane >> 3) & 1) << 3;

    for (int it = 0; it < 8; it++) {
        if (it < 7) cp_wait1(); else cp_wait0();
        __syncthreads();
        if (it + 2 < 8) load_stage((it + 2) % 3, ks0 + (it + 2) * 32);

        __nv_bfloat16* sA = smem + (it % 3) * STG_E;
        __nv_bfloat16* sB = sA + 128 * SKA;
        #pragma unroll
        for (int ks = 0; ks < 32; ks += 16) {
            uint32_t a[2][4];
            #pragma unroll
            for (int mf = 0; mf < 2; mf++)
                ldsm4(a[mf][0], a[mf][1], a[mf][2], a[mf][3],
                      &sA[(wm * 32 + mf * 16 + arow) * SKA + ks + asel]);
            #pragma unroll
            for (int nt = 0; nt < 6; nt++) {
                uint32_t b0, b1, b2, b3;
                ldsm4(b0, b1, b2, b3,
                      &sB[(wn * 96 + nt * 16 + brow) * SKA + ks + bsel]);
                uint32_t bp0[2] = {b0, b1}, bp1[2] = {b2, b3};
                #pragma unroll
                for (int mf = 0; mf < 2; mf++) {
                    mma_bf16(acc[mf][nt * 2],     a[mf], bp0);
                    mma_bf16(acc[mf][nt * 2 + 1], a[mf], bp1);
                }
            }
        }
        __syncthreads();
    }

    float* out = &g_accp[(size_t)blockIdx.y * BDIM * ND];
    #pragma unroll
    for (int mf = 0; mf < 2; mf++)
        #pragma unroll
        for (int nf = 0; nf < 12; nf++) {
            int r = m0 + wm * 32 + mf * 16 + g;
            int c = wn * 96 + nf * 8 + tg * 2;
            *(float2*)&out[(size_t)r * ND + c]       = make_float2(acc[mf][nf][0], acc[mf][nf][1]);
            *(float2*)&out[(size_t)(r + 8) * ND + c] = make_float2(acc[mf][nf][2], acc[mf][nf][3]);
        }
}

// ---------------- k_finish3: 3 steps, 16 rows/block, 512 threads, mma ds@G ----------------
#define SMEMF 181824
__global__ void __launch_bounds__(512) k_finish3(
    const float* __restrict__ cb1, const float* __restrict__ cw2,
    const float* __restrict__ cb2, const float* __restrict__ ow1,
    const float* __restrict__ ob1, const float* __restrict__ ow2,
    const float* __restrict__ ob2, const float* __restrict__ ow3) {
    extern __shared__ char sm[];
    char* p = sm;
    __nv_bfloat16* sG   = (__nv_bfloat16*)p; p += 192 * 200 * 2;   // [192][200]
    __nv_bfloat16* sdsb = (__nv_bfloat16*)p; p += 16 * 200 * 2;    // [16][200]
    float* sW2  = (float*)p; p += 128 * 68 * 4;                    // ow2 padded
    float* sW1c = (float*)p; p += 1280 * 4;                        // ow1[P:] [10][128]
    float* sCw2 = (float*)p; p += 640 * 4;
    float* sb   = (float*)p; p += 336 * 4;                         // cb1|cb2|ob1|ob2|ow3
    float* sacc = (float*)p; p += FR * 192 * 4;
    float* sds  = (float*)p; p += FR * 192 * 4;
    float* sD   = (float*)p; p += FR * 192 * 4;
    float* sh1c = (float*)p; p += FR * 64 * 4;
    float* scv  = (float*)p; p += FR * 12 * 4;
    float* sdzc = (float*)p; p += FR * 12 * 4;
    float* sa1  = (float*)p; p += FR * 128 * 4;
    float* sdz2 = (float*)p;

    const int tid = threadIdx.x, lane = tid & 31, w = tid >> 5;
    const int b0 = blockIdx.x * FR;

    // ---- weights once ----
    for (int i = tid; i < 192 * 96; i += 512) {        // G -> bf16, stride 200
        int m = i / 96, n2 = i % 96;
        float2 v = *(const float2*)&g_G[m * 192 + n2 * 2];
        ((__nv_bfloat162*)sG)[m * 100 + n2] = __floats2bfloat162_rn(v.x, v.y);
    }
    for (int i = tid; i < 8192; i += 512) {
        int j = i >> 6, k = i & 63;
        sW2[j * 68 + k] = ow2[i];
    }
    for (int i = tid; i < 1280; i += 512) {
        int q = i >> 7, j = i & 127;
        sW1c[i] = ow1[(PDIM + q) * 128 + j];
    }
    for (int i = tid; i < 640; i += 512) sCw2[i] = cw2[i];
    if (tid < 64)  sb[tid]       = cb1[tid];
    if (tid < 10)  sb[64 + tid]  = cb2[tid];
    if (tid < 128) sb[80 + tid]  = ob1[tid];
    if (tid < 64)  sb[208 + tid] = ob2[tid];
    if (tid < 64)  sb[272 + tid] = ow3[tid];

    // ---- acc0 = sum of split-K partials; D = 0 ----
    for (int i = tid; i < FR * 48; i += 512) {
        int r = i / 48, n4 = (i % 48) * 4;
        size_t bb = (size_t)(b0 + r);
        float4 s = make_float4(0.f, 0.f, 0.f, 0.f);
        #pragma unroll
        for (int sp = 0; sp < NSPLIT; sp++) {
            float4 v = *(const float4*)&g_accp[((size_t)sp * BDIM + bb) * ND + n4];
            s.x += v.x; s.y += v.y; s.z += v.z; s.w += v.w;
        }
        *(float4*)&sacc[r * 192 + n4] = s;
    }
    for (int i = tid; i < FR * 192; i += 512) sD[i] = 0.f;
    __syncthreads();

    for (int step = 0; step < 3; step++) {
        // h1c = relu(acc[:64] + cb1)
        for (int i = tid; i < FR * 64; i += 512) {
            int r = i >> 6, j = i & 63;
            sh1c[i] = fmaxf(sacc[r * 192 + j] + sb[j], 0.f);
        }
        __syncthreads();
        // cv = sigmoid(h1c @ cw2 + cb2)
        if (tid < FR * 10) {
            int r = tid / 10, q = tid % 10;
            float s = sb[64 + q];
            #pragma unroll 8
            for (int k = 0; k < 64; k++) s += sh1c[r * 64 + k] * sCw2[k * 10 + q];
            scv[r * 12 + q] = 1.f / (1.f + expf(-s));
        }
        __syncthreads();
        // a1 = relu(acc[64:] + ob1 + cv @ ow1[P:])
        for (int i = tid; i < FR * 128; i += 512) {
            int r = i >> 7, j = i & 127;
            float z = sacc[r * 192 + 64 + j] + sb[80 + j];
            #pragma unroll
            for (int q = 0; q < 10; q++) z += scv[r * 12 + q] * sW1c[q * 128 + j];
            sa1[i] = fmaxf(z, 0.f);
        }
        __syncthreads();
        // dz2 = relu'(a1 @ ow2 + ob2) * ow3
        {
            int r = tid >> 5, kp = tid & 31;
            int k2 = kp * 2;
            float s0 = sb[208 + k2], s1 = sb[208 + k2 + 1];
            const float* a1r = &sa1[r * 128];
            #pragma unroll 8
            for (int j = 0; j < 128; j++) {
                float a = a1r[j];
                float2 wv = *(const float2*)&sW2[j * 68 + k2];
                s0 += a * wv.x; s1 += a * wv.y;
            }
            sdz2[r * 64 + k2]     = (s0 > 0.f) ? sb[272 + k2] : 0.f;
            sdz2[r * 64 + k2 + 1] = (s1 > 0.f) ? sb[272 + k2 + 1] : 0.f;
        }
        __syncthreads();
        // dz1 (scaled -0.01) -> sds[64+j]
        for (int s4 = 0; s4 < 4; s4++) {
            int i = tid + s4 * 512;
            int r = i >> 7, j = i & 127;
            const float* dzr = &sdz2[r * 64];
            const float* wr = &sW2[j * 68];
            float s = 0.f;
            #pragma unroll
            for (int k = 0; k < 64; k += 4) {
                float4 dv = *(const float4*)&dzr[k];
                float4 wv = *(const float4*)&wr[k];
                s += dv.x * wv.x + dv.y * wv.y + dv.z * wv.z + dv.w * wv.w;
            }
            sds[r * 192 + 64 + j] = (sa1[i] > 0.f) ? -0.01f * s : 0.f;
        }
        __syncthreads();
        // dzc = (dz1 @ ow1c^T) * cv*(1-cv)
        if (tid < FR * 10) {
            int r = tid / 10, q = tid % 10;
            const float* dsr = &sds[r * 192 + 64];
            const float* wr = &sW1c[q * 128];
            float s = 0.f;
            #pragma unroll
            for (int j = 0; j < 128; j += 4) {
                float4 dv = *(const float4*)&dsr[j];
                float4 wv = *(const float4*)&wr[j];
                s += dv.x * wv.x + dv.y * wv.y + dv.z * wv.z + dv.w * wv.w;
            }
            float c = scv[r * 12 + q];
            sdzc[r * 12 + q] = s * c * (1.f - c);
        }
        __syncthreads();
        // dconstr -> sds[0..64)
        for (int i = tid; i < FR * 64; i += 512) {
            int r = i >> 6, j = i & 63;
            float s = 0.f;
            #pragma unroll
            for (int q = 0; q < 10; q++) s += sdzc[r * 12 + q] * sCw2[j * 10 + q];
            sds[r * 192 + j] = (sacc[r * 192 + j] + sb[j] > 0.f) ? s : 0.f;
        }
        __syncthreads();
        // D += ds
        for (int i = tid; i < FR * 192; i += 512) sD[i] += sds[i];

        if (step < 2) {
            // ds -> bf16 (stride 200)
            for (int i = tid; i < FR * 96; i += 512) {
                int r = i / 96, n2 = i % 96;
                float2 v = *(const float2*)&sds[r * 192 + n2 * 2];
                ((__nv_bfloat162*)sdsb)[r * 100 + n2] = __floats2bfloat162_rn(v.x, v.y);
            }
            __syncthreads();
            // acc += ds @ G via mma (G symmetric -> B[n][k] = G[n][k])
            if (w < 12) {
                int n0 = w * 16;
                float c[2][4] = {{0.f,0.f,0.f,0.f},{0.f,0.f,0.f,0.f}};
                const int arow = lane & 15, asel = (lane >> 4) << 3;
                const int brow = (lane & 7) + ((lane >> 4) << 3), bsel = ((lane >> 3) & 1) << 3;
                #pragma unroll
                for (int ks = 0; ks < 192; ks += 16) {
                    uint32_t a[4];
                    ldsm4(a[0], a[1], a[2], a[3], &sdsb[arow * 200 + ks + asel]);
                    uint32_t b0, b1, b2, b3;
                    ldsm4(b0, b1, b2, b3, &sG[(n0 + brow) * 200 + ks + bsel]);
                    uint32_t bp0[2] = {b0, b1}, bp1[2] = {b2, b3};
                    mma_bf16(c[0], a, bp0);
                    mma_bf16(c[1], a, bp1);
                }
                int g = lane >> 2, tg = lane & 3;
                #pragma unroll
                for (int nt = 0; nt < 2; nt++) {
                    int col = n0 + nt * 8 + tg * 2;
                    sacc[g * 192 + col]           += c[nt][0];
                    sacc[g * 192 + col + 1]       += c[nt][1];
                    sacc[(g + 8) * 192 + col]     += c[nt][2];
                    sacc[(g + 8) * 192 + col + 1] += c[nt][3];
                }
            }
        }
        __syncthreads();
    }

    // write dcat (bf16, padded to SK2)
    for (int i = tid; i < FR * SK2; i += 512) {
        int r = i / SK2, n = i % SK2;
        g_dcat[(size_t)(b0 + r) * SK2 + n] =
            __float2bfloat16(n < 192 ? sD[r * 192 + n] : 0.f);
    }
}

// ---------------- GEMM2: out = params0 + D x Wcat^T, n-tile 64 ----------------
__global__ void __launch_bounds__(256, 2) k_gemm2(float* __restrict__ outp) {
    extern __shared__ char smem_raw[];
    __nv_bfloat16* sA = (__nv_bfloat16*)smem_raw;          // 128 x 200
    __nv_bfloat16* sB = sA + 128 * SK2;                    // 64 x 200
    const int tid = threadIdx.x, lane = tid & 31, w = tid >> 5;
    const int wm = w >> 1, wn = w & 1, g = lane >> 2, tg = lane & 3;
    const int m0 = blockIdx.x * 128;
    const int n0 = blockIdx.y * 64;

    #pragma unroll
    for (int i = 0; i < 12; i++) {
        int idx = tid + i * 256;
        int row = idx / 24, ch = idx % 24;
        cp16(&sA[row * SK2 + ch * 8], &g_dcat[(size_t)(m0 + row) * SK2 + ch * 8]);
    }
    for (int idx = tid; idx < 1600; idx += 256) {
        int row = idx / 25, ch = idx % 25;
        if (ch < 24)
            cp16(&sB[row * SK2 + ch * 8], &g_WBt[(size_t)(n0 + row) * SK2 + ch * 8]);
    }
    cp_commit();

    float acc[2][4][4];
    #pragma unroll
    for (int i = 0; i < 2; i++)
        #pragma unroll
        for (int j = 0; j < 4; j++)
            #pragma unroll
            for (int q = 0; q < 4; q++) acc[i][j][q] = 0.f;

    cp_wait0();
    __syncthreads();

    const int arow = lane & 15, asel = (lane >> 4) << 3;
    const int brow = (lane & 7) + ((lane >> 4) << 3), bsel = ((lane >> 3) & 1) << 3;

    #pragma unroll
    for (int ks = 0; ks < ND; ks += 16) {
        uint32_t a[2][4];
        #pragma unroll
        for (int mf = 0; mf < 2; mf++)
            ldsm4(a[mf][0], a[mf][1], a[mf][2], a[mf][3],
                  &sA[(wm * 32 + mf * 16 + arow) * SK2 + ks + asel]);
        #pragma unroll
        for (int nt = 0; nt < 2; nt++) {
            uint32_t b0, b1, b2, b3;
            ldsm4(b0, b1, b2, b3,
                  &sB[(wn * 32 + nt * 16 + brow) * SK2 + ks + bsel]);
            uint32_t bp0[2] = {b0, b1}, bp1[2] = {b2, b3};
            #pragma unroll
            for (int mf = 0; mf < 2; mf++) {
                mma_bf16(acc[mf][nt * 2],     a[mf], bp0);
                mma_bf16(acc[mf][nt * 2 + 1], a[mf], bp1);
            }
        }
    }

    #pragma unroll
    for (int mf = 0; mf < 2; mf++)
        #pragma unroll
        for (int nf = 0; nf < 4; nf++) {
            int r = m0 + wm * 32 + mf * 16 + g;
            int c = n0 + wn * 32 + nf * 8 + tg * 2;
            size_t i0 = (size_t)r * PDIM + c;
            size_t i1 = i0 + (size_t)8 * PDIM;
            float2 pv0 = *(const float2*)&g_params[i0];
            float2 pv1 = *(const float2*)&g_params[i1];
            *(float2*)&outp[i0] = make_float2(pv0.x + acc[mf][nf][0], pv0.y + acc[mf][nf][1]);
            *(float2*)&outp[i1] = make_float2(pv1.x + acc[mf][nf][2], pv1.y + acc[mf][nf][3]);
        }
}

// ---------------- launch ----------------
extern "C" void kernel_launch(void* const* d_in, const int* in_sizes, int n_in,
                              void* d_out, int out_size) {
    const float* tp   = (const float*)d_in[0];
    const float* cons = (const float*)d_in[1];
    // d_in[2] transverse_field, d_in[3] coupling, d_in[14] ob3 : dead
    const float* mp   = (const float*)d_in[4];
    const float* cw1  = (const float*)d_in[5];
    const float* cb1  = (const float*)d_in[6];
    const float* cw2  = (const float*)d_in[7];
    const float* cb2  = (const float*)d_in[8];
    const float* ow1  = (const float*)d_in[9];
    const float* ob1  = (const float*)d_in[10];
    const float* ow2  = (const float*)d_in[11];
    const float* ob2  = (const float*)d_in[12];
    const float* ow3  = (const float*)d_in[13];
    float* outp = (float*)d_out;

    const int SMEM1 = 3 * (128 * SKA + ND * SKA) * 2;   // 76800
    const int SMEM2 = (128 * SK2 + 64 * SK2) * 2;       // 76800
    cudaFuncSetAttribute(k_gemm1,   cudaFuncAttributeMaxDynamicSharedMemorySize, SMEM1);
    cudaFuncSetAttribute(k_gemm2,   cudaFuncAttributeMaxDynamicSharedMemorySize, SMEM2);
    cudaFuncSetAttribute(k_finish3, cudaFuncAttributeMaxDynamicSharedMemorySize, SMEMF);

    k_setup<<<NB_CM + NB_GRAM + NB_PREP, 256>>>(mp, cw1, ow1);
    k_init<<<(BDIM * PDIM / 4) / 256, 256>>>(tp, cons);
    k_gemm1<<<dim3(16, NSPLIT), 256, SMEM1>>>();
    k_finish3<<<BDIM / FR, 512, SMEMF>>>(cb1, cw2, cb2, ow1, ob1, ow2, ob2, ow3);
    k_gemm2<<<dim3(16, 64), 256, SMEM2>>>(outp);
}